// round 9
// baseline (speedup 1.0000x reference)
#include <cuda_runtime.h>
#include <cuda_fp16.h>

// FakeReviewGNN: 2-layer GCN, N=100000, 7 -> 64 -> 32 -> 2.
// CSR-free scatter pipeline, both scatters in fp16 (minimal atomic count):
//   k_count     : dst histogram (cnt pre-zeroed / reset by k_final)
//   k_prep      : dinv = rsqrt(cnt+1); xdh = x*dinv as 8 halves; ph init = xdh
//   k_scatter16h: ph[dst] += xdh[src]          (1 x red.v4.f16x2 / edge)
//   k_transform : 4 nodes/warp; phase2 uses packed fma.rn.f32x2 -> g2 fp16
//   k_scatter32h: s2h[dst] += g2h[src]         (4 x red.v4.f16x2 / edge)
//   k_final     : h2 = relu(dinv*s2+b2); log_softmax(h2@Wc+bc); reset cnt

#define MAXN 100000
#define F1 64
#define F2 32

__device__ int   d_cnt [MAXN];          // zero-init; k_final resets after use
__device__ float d_dinv[MAXN];
__device__ __align__(128) __half d_xdh[MAXN * 8];    // x*dinv, fp16, pad 7->8
__device__ __align__(128) __half d_ph [MAXN * 8];    // aggregated, fp16
__device__ __align__(128) __half d_g2h[MAXN * F2];
__device__ __align__(128) __half d_s2h[MAXN * F2];

__device__ __forceinline__ void red_add_v4h2(uint4* addr, uint4 v) {
    asm volatile("red.global.add.noftz.v4.f16x2 [%0], {%1, %2, %3, %4};"
                 :: "l"(addr), "r"(v.x), "r"(v.y), "r"(v.z), "r"(v.w)
                 : "memory");
}

// ---- histogram (cnt assumed zero on entry) ---------------------------------

__global__ void k_count_v4(const int4* __restrict__ dst4, int E4) {
    int i = blockIdx.x * blockDim.x + threadIdx.x;
    if (i >= E4) return;
    int4 d = dst4[i];
    atomicAdd(&d_cnt[d.x], 1);
    atomicAdd(&d_cnt[d.y], 1);
    atomicAdd(&d_cnt[d.z], 1);
    atomicAdd(&d_cnt[d.w], 1);
}

__global__ void k_count_sc(const int* __restrict__ dst, int E) {
    int i = blockIdx.x * blockDim.x + threadIdx.x;
    if (i < E) atomicAdd(&d_cnt[dst[i]], 1);
}

// ---- prep: dinv, xdh = x*dinv as fp16 (pad 7->8), ph init = xdh ------------

__global__ void k_prep(const float* __restrict__ x, int n) {
    int i = blockIdx.x * blockDim.x + threadIdx.x;
    if (i >= n) return;
    float dv = rsqrtf((float)(d_cnt[i] + 1));   // +1 self loop
    d_dinv[i] = dv;
    const float* xi = x + (long long)i * 7;
    __half2 h0 = __floats2half2_rn(xi[0] * dv, xi[1] * dv);
    __half2 h1 = __floats2half2_rn(xi[2] * dv, xi[3] * dv);
    __half2 h2 = __floats2half2_rn(xi[4] * dv, xi[5] * dv);
    __half2 h3 = __floats2half2_rn(xi[6] * dv, 0.0f);
    uint4 v;
    v.x = *reinterpret_cast<unsigned*>(&h0);
    v.y = *reinterpret_cast<unsigned*>(&h1);
    v.z = *reinterpret_cast<unsigned*>(&h2);
    v.w = *reinterpret_cast<unsigned*>(&h3);
    reinterpret_cast<uint4*>(d_xdh)[i] = v;
    reinterpret_cast<uint4*>(d_ph )[i] = v;
}

// ---- layer-1 scatter: ph[dst] += xdh[src], 1 red.v4.f16x2 / edge -----------

__global__ void k_scatter16h(const int* __restrict__ src,
                             const int* __restrict__ dst, int E) {
    int e = blockIdx.x * blockDim.x + threadIdx.x;
    if (e >= E) return;
    int u = src[e], v = dst[e];
    uint4 val = reinterpret_cast<const uint4*>(d_xdh)[u];
    red_add_v4h2(&reinterpret_cast<uint4*>(d_ph)[v], val);
}

// ---- fused dense transform: 4 nodes/warp, phase-2 packed f32x2 FMA ---------
// block = 256 threads = 8 warps = 32 nodes

__global__ void k_transform(const float* __restrict__ W1,
                            const float* __restrict__ b1,
                            const float* __restrict__ W2, int n) {
    __shared__ float              W1s[7 * F1];
    __shared__ float              b1s[F1];
    __shared__ unsigned long long W2d[F1 * F2];   // (w,w) duplicated, 16 KB
    __shared__ float              hs2[8][F1][4];  // [warp][k][node], 8 KB

    for (int i = threadIdx.x; i < 7 * F1; i += blockDim.x) W1s[i] = W1[i];
    for (int i = threadIdx.x; i < F1;     i += blockDim.x) b1s[i] = b1[i];
    for (int i = threadIdx.x; i < F1 * F2; i += blockDim.x) {
        unsigned wb = __float_as_uint(W2[i]);
        unsigned long long dup;
        asm("mov.b64 %0, {%1, %1};" : "=l"(dup) : "r"(wb));
        W2d[i] = dup;
    }
    __syncthreads();

    int warp  = threadIdx.x >> 5;
    int lane  = threadIdx.x & 31;
    int base4 = blockIdx.x * 32 + warp * 4;
    if (base4 >= n) return;

    // coalesced fetch of p for 4 nodes: lane = node*8 + feat (fp16 payload)
    int li = lane >> 3;
    int lf = lane & 7;
    int node_ld = base4 + li; if (node_ld >= n) node_ld = n - 1;
    float pv  = __half2float(d_ph[node_ld * 8 + lf]);
    float dvv = d_dinv[node_ld];

    // phase 1: h1 = relu(dinv*(p@W1)+b1); store transposed hs2[k][node]
    float dv[4];
    #pragma unroll
    for (int i = 0; i < 4; i++) {
        dv[i] = __shfl_sync(0xffffffffu, dvv, i * 8);
        float a0 = 0.0f, a1 = 0.0f;
        #pragma unroll
        for (int k = 0; k < 7; k++) {
            float pk = __shfl_sync(0xffffffffu, pv, i * 8 + k);
            a0 += pk * W1s[k * F1 + lane];
            a1 += pk * W1s[k * F1 + 32 + lane];
        }
        hs2[warp][lane]     [i] = fmaxf(dv[i] * a0 + b1s[lane],      0.0f);
        hs2[warp][lane + 32][i] = fmaxf(dv[i] * a1 + b1s[lane + 32], 0.0f);
    }
    __syncwarp();

    // phase 2: g2 = (h1 @ W2) * dinv via packed f32x2 FMA
    unsigned long long acc01 = 0ull, acc23 = 0ull;   // (0.0f, 0.0f)
    #pragma unroll
    for (int k = 0; k < F1; k++) {
        unsigned long long wp = W2d[k * F2 + lane];  // (w,w) LDS.64
        ulonglong2 h = *reinterpret_cast<const ulonglong2*>(&hs2[warp][k][0]);
        asm("fma.rn.f32x2 %0, %1, %2, %0;" : "+l"(acc01) : "l"(h.x), "l"(wp));
        asm("fma.rn.f32x2 %0, %1, %2, %0;" : "+l"(acc23) : "l"(h.y), "l"(wp));
    }

    unsigned r0, r1, r2, r3;
    asm("mov.b64 {%0, %1}, %2;" : "=r"(r0), "=r"(r1) : "l"(acc01));
    asm("mov.b64 {%0, %1}, %2;" : "=r"(r2), "=r"(r3) : "l"(acc23));
    float accs[4] = {__uint_as_float(r0), __uint_as_float(r1),
                     __uint_as_float(r2), __uint_as_float(r3)};

    #pragma unroll
    for (int i = 0; i < 4; i++) {
        int node = base4 + i;
        if (node < n) {
            __half g = __float2half(accs[i] * dv[i]);
            d_g2h[(node << 5) + lane] = g;
            d_s2h[(node << 5) + lane] = g;   // self-loop init
        }
    }
}

// ---- layer-2 scatter: s2h[dst] += g2h[src], 4 red.v4.f16x2 / edge ----------

__global__ void k_scatter32h(const int* __restrict__ src,
                             const int* __restrict__ dst, int E) {
    long long idx = (long long)blockIdx.x * blockDim.x + threadIdx.x;
    int e = (int)(idx >> 2);
    int c = (int)(idx & 3);
    if (e >= E) return;
    int u = src[e], v = dst[e];
    uint4 val = reinterpret_cast<const uint4*>(d_g2h)[(long long)u * 4 + c];
    red_add_v4h2(&reinterpret_cast<uint4*>(d_s2h)[(long long)v * 4 + c], val);
}

// ---- final: relu + classifier + log_softmax + cnt reset (thread/node) ------

__global__ void k_final(const float* __restrict__ b2,
                        const float* __restrict__ Wc,
                        const float* __restrict__ bc,
                        float* __restrict__ out, int n) {
    int node = blockIdx.x * blockDim.x + threadIdx.x;
    if (node >= n) return;

    float dv = d_dinv[node];
    const uint4* s4 = reinterpret_cast<const uint4*>(d_s2h) + (long long)node * 4;
    float l0 = bc[0], l1 = bc[1];

    #pragma unroll
    for (int j = 0; j < 4; j++) {
        uint4 q = s4[j];
        unsigned w[4] = {q.x, q.y, q.z, q.w};
        #pragma unroll
        for (int t = 0; t < 4; t++) {
            float2 v = __half22float2(*reinterpret_cast<const __half2*>(&w[t]));
            int k = j * 8 + t * 2;
            float h0 = fmaxf(dv * v.x + b2[k],     0.0f);
            float h1 = fmaxf(dv * v.y + b2[k + 1], 0.0f);
            l0 += h0 * Wc[k * 2]     + h1 * Wc[k * 2 + 2];
            l1 += h0 * Wc[k * 2 + 1] + h1 * Wc[k * 2 + 3];
        }
    }

    float m   = fmaxf(l0, l1);
    float lse = m + logf(expf(l0 - m) + expf(l1 - m));
    out[(long long)node * 2]     = l0 - lse;
    out[(long long)node * 2 + 1] = l1 - lse;
    d_cnt[node] = 0;   // reset histogram for next replay (deterministic)
}

// ---- launch ----------------------------------------------------------------

extern "C" void kernel_launch(void* const* d_in, const int* in_sizes, int n_in,
                              void* d_out, int out_size) {
    const float* x  = (const float*)d_in[0];
    const int*   ei = (const int*)  d_in[1];
    const float* W1 = (const float*)d_in[2];
    const float* b1 = (const float*)d_in[3];
    const float* W2 = (const float*)d_in[4];
    const float* b2 = (const float*)d_in[5];
    const float* Wc = (const float*)d_in[6];
    const float* bc = (const float*)d_in[7];
    float* out = (float*)d_out;

    int n = in_sizes[0] / 7;     // 100000
    int E = in_sizes[1] / 2;     // 1600000
    const int* src = ei;
    const int* dst = ei + E;

    const int T = 256;

    bool vec_ok = (E % 4 == 0) && ((((unsigned long long)dst) & 15ull) == 0);
    if (vec_ok) {
        int E4 = E / 4;
        k_count_v4<<<(E4 + T - 1) / T, T>>>((const int4*)dst, E4);
    } else {
        k_count_sc<<<(E + T - 1) / T, T>>>(dst, E);
    }

    k_prep<<<(n + T - 1) / T, T>>>(x, n);

    k_scatter16h<<<(E + T - 1) / T, T>>>(src, dst, E);

    k_transform<<<(n + 31) / 32, T>>>(W1, b1, W2, n);

    long long w2 = (long long)E * 4;
    k_scatter32h<<<(unsigned)((w2 + T - 1) / T), T>>>(src, dst, E);

    k_final<<<(n + T - 1) / T, T>>>(b2, Wc, bc, out, n);
}

// round 10
// speedup vs baseline: 1.1243x; 1.1243x over previous
#include <cuda_runtime.h>
#include <cuda_fp16.h>

// FakeReviewGNN: 2-layer GCN, N=100000, 7 -> 64 -> 32 -> 2.
// CSR-free scatter pipeline, both scatters fp16:
//   k_count     : dst histogram (cnt pre-zeroed / reset by k_final)
//   k_prep      : dinv = rsqrt(cnt+1); xdh = x*dinv as 8 halves; ph init = xdh
//   k_scatter16h: ph[dst] += xdh[src]          (1 x red.v4.f16x2 / edge)
//   k_transform : 8 nodes/warp, LDS-amortized two-stage GEMV -> g2 fp16
//   k_scatter32h: s2h[dst] += g2h[src]         (4 x red.v4.f16x2 / edge)
//   k_final     : h2 = relu(dinv*s2+b2); log_softmax(h2@Wc+bc); reset cnt

#define MAXN 100000
#define F1 64
#define F2 32

__device__ int   d_cnt [MAXN];          // zero-init; k_final resets after use
__device__ float d_dinv[MAXN];
__device__ __align__(128) __half d_xdh[MAXN * 8];
__device__ __align__(128) __half d_ph [MAXN * 8];
__device__ __align__(128) __half d_g2h[MAXN * F2];
__device__ __align__(128) __half d_s2h[MAXN * F2];

__device__ __forceinline__ void red_add_v4h2(uint4* addr, uint4 v) {
    asm volatile("red.global.add.noftz.v4.f16x2 [%0], {%1, %2, %3, %4};"
                 :: "l"(addr), "r"(v.x), "r"(v.y), "r"(v.z), "r"(v.w)
                 : "memory");
}

// ---- histogram (cnt assumed zero on entry) ---------------------------------

__global__ void k_count_v4(const int4* __restrict__ dst4, int E4) {
    int i = blockIdx.x * blockDim.x + threadIdx.x;
    if (i >= E4) return;
    int4 d = dst4[i];
    atomicAdd(&d_cnt[d.x], 1);
    atomicAdd(&d_cnt[d.y], 1);
    atomicAdd(&d_cnt[d.z], 1);
    atomicAdd(&d_cnt[d.w], 1);
}

__global__ void k_count_sc(const int* __restrict__ dst, int E) {
    int i = blockIdx.x * blockDim.x + threadIdx.x;
    if (i < E) atomicAdd(&d_cnt[dst[i]], 1);
}

// ---- prep: dinv, xdh = x*dinv as fp16 (pad 7->8), ph init = xdh ------------

__global__ void k_prep(const float* __restrict__ x, int n) {
    int i = blockIdx.x * blockDim.x + threadIdx.x;
    if (i >= n) return;
    float dv = rsqrtf((float)(d_cnt[i] + 1));   // +1 self loop
    d_dinv[i] = dv;
    const float* xi = x + (long long)i * 7;
    __half2 h0 = __floats2half2_rn(xi[0] * dv, xi[1] * dv);
    __half2 h1 = __floats2half2_rn(xi[2] * dv, xi[3] * dv);
    __half2 h2 = __floats2half2_rn(xi[4] * dv, xi[5] * dv);
    __half2 h3 = __floats2half2_rn(xi[6] * dv, 0.0f);
    uint4 v;
    v.x = *reinterpret_cast<unsigned*>(&h0);
    v.y = *reinterpret_cast<unsigned*>(&h1);
    v.z = *reinterpret_cast<unsigned*>(&h2);
    v.w = *reinterpret_cast<unsigned*>(&h3);
    reinterpret_cast<uint4*>(d_xdh)[i] = v;
    reinterpret_cast<uint4*>(d_ph )[i] = v;
}

// ---- layer-1 scatter: ph[dst] += xdh[src], 1 red.v4.f16x2 / edge -----------

__global__ void k_scatter16h(const int* __restrict__ src,
                             const int* __restrict__ dst, int E) {
    int e = blockIdx.x * blockDim.x + threadIdx.x;
    if (e >= E) return;
    int u = src[e], v = dst[e];
    uint4 val = reinterpret_cast<const uint4*>(d_xdh)[u];
    red_add_v4h2(&reinterpret_cast<uint4*>(d_ph)[v], val);
}

// ---- fused dense transform: 8 nodes per warp, LDS-amortized ----------------
// block = 256 threads = 8 warps = 64 nodes

__global__ void k_transform(const float* __restrict__ W1,
                            const float* __restrict__ b1,
                            const float* __restrict__ W2, int n) {
    __shared__ float W1s[7 * F1];       // 1.75 KB
    __shared__ float b1s[F1];
    __shared__ float W2s[F1 * F2];      // 8 KB
    __shared__ float hs[8][8][F1];      // [warp][node][feature], 16 KB

    for (int i = threadIdx.x; i < 7 * F1;  i += blockDim.x) W1s[i] = W1[i];
    for (int i = threadIdx.x; i < F1;      i += blockDim.x) b1s[i] = b1[i];
    for (int i = threadIdx.x; i < F1 * F2; i += blockDim.x) W2s[i] = W2[i];
    __syncthreads();

    int warp  = threadIdx.x >> 5;
    int lane  = threadIdx.x & 31;
    int base8 = blockIdx.x * 64 + warp * 8;   // first of this warp's 8 nodes
    if (base8 >= n) return;

    // two coalesced 64B fp16 loads fetch p for the 8 nodes:
    // load j: lane = (node - 4j)*8 + feat
    int li = lane >> 3;
    int lf = lane & 7;
    int nl0 = base8 + li;     if (nl0 >= n) nl0 = n - 1;
    int nl1 = base8 + 4 + li; if (nl1 >= n) nl1 = n - 1;
    float pv0  = __half2float(d_ph[nl0 * 8 + lf]);
    float pv1  = __half2float(d_ph[nl1 * 8 + lf]);
    float dvv0 = d_dinv[nl0];
    float dvv1 = d_dinv[nl1];

    // phase 1: h1 = relu(dinv*(p@W1)+b1) for the 8 nodes
    float dv[8];
    #pragma unroll
    for (int i = 0; i < 8; i++) {
        float pvs = (i < 4) ? pv0 : pv1;
        float dvs = (i < 4) ? dvv0 : dvv1;
        int   sl  = (i & 3) * 8;
        dv[i] = __shfl_sync(0xffffffffu, dvs, sl);
        float a0 = 0.0f, a1 = 0.0f;
        #pragma unroll
        for (int k = 0; k < 7; k++) {
            float pk = __shfl_sync(0xffffffffu, pvs, sl + k);
            a0 += pk * W1s[k * F1 + lane];
            a1 += pk * W1s[k * F1 + 32 + lane];
        }
        hs[warp][i][lane]      = fmaxf(dv[i] * a0 + b1s[lane],      0.0f);
        hs[warp][i][lane + 32] = fmaxf(dv[i] * a1 + b1s[lane + 32], 0.0f);
    }
    __syncwarp();

    // phase 2: g2 = (h1 @ W2) * dinv, k-step 4, float4 h-broadcasts
    float acc[8] = {0, 0, 0, 0, 0, 0, 0, 0};
    #pragma unroll
    for (int ks = 0; ks < F1; ks += 4) {
        float w0 = W2s[(ks    ) * F2 + lane];
        float w1 = W2s[(ks + 1) * F2 + lane];
        float w2 = W2s[(ks + 2) * F2 + lane];
        float w3 = W2s[(ks + 3) * F2 + lane];
        #pragma unroll
        for (int i = 0; i < 8; i++) {
            float4 h = *reinterpret_cast<const float4*>(&hs[warp][i][ks]);
            acc[i] += h.x * w0 + h.y * w1 + h.z * w2 + h.w * w3;
        }
    }

    #pragma unroll
    for (int i = 0; i < 8; i++) {
        int node = base8 + i;
        if (node < n) {
            __half g = __float2half(acc[i] * dv[i]);
            d_g2h[(node << 5) + lane] = g;
            d_s2h[(node << 5) + lane] = g;   // self-loop init
        }
    }
}

// ---- layer-2 scatter: s2h[dst] += g2h[src], 4 red.v4.f16x2 / edge ----------

__global__ void k_scatter32h(const int* __restrict__ src,
                             const int* __restrict__ dst, int E) {
    long long idx = (long long)blockIdx.x * blockDim.x + threadIdx.x;
    int e = (int)(idx >> 2);
    int c = (int)(idx & 3);
    if (e >= E) return;
    int u = src[e], v = dst[e];
    uint4 val = reinterpret_cast<const uint4*>(d_g2h)[(long long)u * 4 + c];
    red_add_v4h2(&reinterpret_cast<uint4*>(d_s2h)[(long long)v * 4 + c], val);
}

// ---- final: relu + classifier + log_softmax + cnt reset (thread/node) ------

__global__ void k_final(const float* __restrict__ b2,
                        const float* __restrict__ Wc,
                        const float* __restrict__ bc,
                        float* __restrict__ out, int n) {
    int node = blockIdx.x * blockDim.x + threadIdx.x;
    if (node >= n) return;

    float dv = d_dinv[node];
    const uint4* s4 = reinterpret_cast<const uint4*>(d_s2h) + (long long)node * 4;
    float l0 = bc[0], l1 = bc[1];

    #pragma unroll
    for (int j = 0; j < 4; j++) {
        uint4 q = s4[j];
        unsigned w[4] = {q.x, q.y, q.z, q.w};
        #pragma unroll
        for (int t = 0; t < 4; t++) {
            float2 v = __half22float2(*reinterpret_cast<const __half2*>(&w[t]));
            int k = j * 8 + t * 2;
            float h0 = fmaxf(dv * v.x + b2[k],     0.0f);
            float h1 = fmaxf(dv * v.y + b2[k + 1], 0.0f);
            l0 += h0 * Wc[k * 2]     + h1 * Wc[k * 2 + 2];
            l1 += h0 * Wc[k * 2 + 1] + h1 * Wc[k * 2 + 3];
        }
    }

    float m   = fmaxf(l0, l1);
    float lse = m + logf(expf(l0 - m) + expf(l1 - m));
    out[(long long)node * 2]     = l0 - lse;
    out[(long long)node * 2 + 1] = l1 - lse;
    d_cnt[node] = 0;   // reset histogram for next replay (deterministic)
}

// ---- launch ----------------------------------------------------------------

extern "C" void kernel_launch(void* const* d_in, const int* in_sizes, int n_in,
                              void* d_out, int out_size) {
    const float* x  = (const float*)d_in[0];
    const int*   ei = (const int*)  d_in[1];
    const float* W1 = (const float*)d_in[2];
    const float* b1 = (const float*)d_in[3];
    const float* W2 = (const float*)d_in[4];
    const float* b2 = (const float*)d_in[5];
    const float* Wc = (const float*)d_in[6];
    const float* bc = (const float*)d_in[7];
    float* out = (float*)d_out;

    int n = in_sizes[0] / 7;     // 100000
    int E = in_sizes[1] / 2;     // 1600000
    const int* src = ei;
    const int* dst = ei + E;

    const int T = 256;

    bool vec_ok = (E % 4 == 0) && ((((unsigned long long)dst) & 15ull) == 0);
    if (vec_ok) {
        int E4 = E / 4;
        k_count_v4<<<(E4 + T - 1) / T, T>>>((const int4*)dst, E4);
    } else {
        k_count_sc<<<(E + T - 1) / T, T>>>(dst, E);
    }

    k_prep<<<(n + T - 1) / T, T>>>(x, n);

    k_scatter16h<<<(E + T - 1) / T, T>>>(src, dst, E);

    k_transform<<<(n + 63) / 64, T>>>(W1, b1, W2, n);

    long long w2 = (long long)E * 4;
    k_scatter32h<<<(unsigned)((w2 + T - 1) / T), T>>>(src, dst, E);

    k_final<<<(n + T - 1) / T, T>>>(b2, Wc, bc, out, n);
}

// round 11
// speedup vs baseline: 1.3250x; 1.1785x over previous
#include <cuda_runtime.h>
#include <cuda_fp16.h>

// FakeReviewGNN: 2-layer GCN, N=100000, 7 -> 64 -> 32 -> 2.
// CSR-free scatter pipeline, both scatters fp16; transform on tensor cores:
//   k_count     : dst histogram (cnt pre-zeroed / reset by k_final)
//   k_prep      : dinv = rsqrt(cnt+1); xdh = x*dinv as 8 halves; ph init = xdh
//   k_scatter16h: ph[dst] += xdh[src]          (1 x red.v4.f16x2 / edge)
//   k_transform : HMMA: [16n x 8] @ W1 -> relu -> @ W2, C-frag -> A-frag in regs
//   k_scatter32h: s2h[dst] += g2h[src]         (4 x red.v4.f16x2 / edge)
//   k_final     : h2 = relu(dinv*s2+b2); log_softmax(h2@Wc+bc); reset cnt

#define MAXN 100000
#define F1 64
#define F2 32

__device__ int   d_cnt [MAXN];          // zero-init; k_final resets after use
__device__ float d_dinv[MAXN];
__device__ __align__(128) __half d_xdh[MAXN * 8];
__device__ __align__(128) __half d_ph [MAXN * 8];
__device__ __align__(128) __half d_g2h[MAXN * F2];
__device__ __align__(128) __half d_s2h[MAXN * F2];

__device__ __forceinline__ void red_add_v4h2(uint4* addr, uint4 v) {
    asm volatile("red.global.add.noftz.v4.f16x2 [%0], {%1, %2, %3, %4};"
                 :: "l"(addr), "r"(v.x), "r"(v.y), "r"(v.z), "r"(v.w)
                 : "memory");
}

__device__ __forceinline__ unsigned smem_u32(const void* p) {
    return (unsigned)__cvta_generic_to_shared(p);
}

// ---- histogram (cnt assumed zero on entry) ---------------------------------

__global__ void k_count_v4(const int4* __restrict__ dst4, int E4) {
    int i = blockIdx.x * blockDim.x + threadIdx.x;
    if (i >= E4) return;
    int4 d = dst4[i];
    atomicAdd(&d_cnt[d.x], 1);
    atomicAdd(&d_cnt[d.y], 1);
    atomicAdd(&d_cnt[d.z], 1);
    atomicAdd(&d_cnt[d.w], 1);
}

__global__ void k_count_sc(const int* __restrict__ dst, int E) {
    int i = blockIdx.x * blockDim.x + threadIdx.x;
    if (i < E) atomicAdd(&d_cnt[dst[i]], 1);
}

// ---- prep: dinv, xdh = x*dinv as fp16 (pad 7->8), ph init = xdh ------------

__global__ void k_prep(const float* __restrict__ x, int n) {
    int i = blockIdx.x * blockDim.x + threadIdx.x;
    if (i >= n) return;
    float dv = rsqrtf((float)(d_cnt[i] + 1));   // +1 self loop
    d_dinv[i] = dv;
    const float* xi = x + (long long)i * 7;
    __half2 h0 = __floats2half2_rn(xi[0] * dv, xi[1] * dv);
    __half2 h1 = __floats2half2_rn(xi[2] * dv, xi[3] * dv);
    __half2 h2 = __floats2half2_rn(xi[4] * dv, xi[5] * dv);
    __half2 h3 = __floats2half2_rn(xi[6] * dv, 0.0f);
    uint4 v;
    v.x = *reinterpret_cast<unsigned*>(&h0);
    v.y = *reinterpret_cast<unsigned*>(&h1);
    v.z = *reinterpret_cast<unsigned*>(&h2);
    v.w = *reinterpret_cast<unsigned*>(&h3);
    reinterpret_cast<uint4*>(d_xdh)[i] = v;
    reinterpret_cast<uint4*>(d_ph )[i] = v;
}

// ---- layer-1 scatter: ph[dst] += xdh[src], 1 red.v4.f16x2 / edge -----------

__global__ void k_scatter16h(const int* __restrict__ src,
                             const int* __restrict__ dst, int E) {
    int e = blockIdx.x * blockDim.x + threadIdx.x;
    if (e >= E) return;
    int u = src[e], v = dst[e];
    uint4 val = reinterpret_cast<const uint4*>(d_xdh)[u];
    red_add_v4h2(&reinterpret_cast<uint4*>(d_ph)[v], val);
}

// ---- tensor-core transform: 16 nodes/warp, 128 nodes/block -----------------

__global__ void __launch_bounds__(256) k_transform(const float* __restrict__ W1,
                                                   const float* __restrict__ b1,
                                                   const float* __restrict__ W2,
                                                   int n) {
    __shared__ __half W1h[8][F1];        // k-padded fp16 W1, 1 KB
    __shared__ __half W2h[F1][F2];       // fp16 W2, 4 KB
    __shared__ float  b1s[F1];
    __shared__ __half ph_s[128][8];      // 2 KB
    __shared__ float  dinv_s[128];

    int tid = threadIdx.x;
    for (int i = tid; i < 8 * F1; i += 256) {
        int k = i >> 6, c = i & 63;
        W1h[k][c] = __float2half((k < 7) ? W1[k * F1 + c] : 0.0f);
    }
    for (int i = tid; i < F1 * F2; i += 256)
        W2h[i >> 5][i & 31] = __float2half(W2[i]);
    if (tid < F1) b1s[tid] = b1[tid];

    int blockbase = blockIdx.x * 128;
    if (tid < 128) {
        int node = blockbase + tid; if (node >= n) node = n - 1;
        *reinterpret_cast<uint4*>(&ph_s[tid][0]) =
            reinterpret_cast<const uint4*>(d_ph)[node];
        dinv_s[tid] = d_dinv[node];
    }
    __syncthreads();

    int warp = tid >> 5;
    int lane = tid & 31;
    int r0   = warp * 16;                // this warp's 16 node rows

    // ---- phase 1: C1[16x64] = P[16x8] @ W1h[8x64], 8 x mma.m16n8k8 ----
    unsigned a0, a1;
    {
        unsigned addr = smem_u32(&ph_s[r0 + (lane & 15)][0]);
        asm volatile("ldmatrix.sync.aligned.m8n8.x2.shared.b16 {%0,%1}, [%2];"
                     : "=r"(a0), "=r"(a1) : "r"(addr));
    }
    unsigned bw1[8];
    {
        int k  = lane & 7;
        int t4 = (lane >> 3) & 3;
        unsigned ad0 = smem_u32(&W1h[k][t4 * 8]);
        unsigned ad1 = smem_u32(&W1h[k][32 + t4 * 8]);
        asm volatile("ldmatrix.sync.aligned.m8n8.x4.trans.shared.b16 {%0,%1,%2,%3}, [%4];"
                     : "=r"(bw1[0]), "=r"(bw1[1]), "=r"(bw1[2]), "=r"(bw1[3])
                     : "r"(ad0));
        asm volatile("ldmatrix.sync.aligned.m8n8.x4.trans.shared.b16 {%0,%1,%2,%3}, [%4];"
                     : "=r"(bw1[4]), "=r"(bw1[5]), "=r"(bw1[6]), "=r"(bw1[7])
                     : "r"(ad1));
    }

    float c1[8][4];
    #pragma unroll
    for (int nn = 0; nn < 8; nn++) {
        c1[nn][0] = c1[nn][1] = c1[nn][2] = c1[nn][3] = 0.0f;
        asm volatile(
            "mma.sync.aligned.m16n8k8.row.col.f32.f16.f16.f32 "
            "{%0,%1,%2,%3}, {%4,%5}, {%6}, {%0,%1,%2,%3};"
            : "+f"(c1[nn][0]), "+f"(c1[nn][1]), "+f"(c1[nn][2]), "+f"(c1[nn][3])
            : "r"(a0), "r"(a1), "r"(bw1[nn]));
    }

    // ---- epilogue 1: h1 = relu(dv*c1 + b1), pack to phase-2 A fragments ----
    // C m16n8 frag: c0,c1 at (row g, col 2t,2t+1); c2,c3 at (row g+8, same).
    // A m16n8k16 frag halves have the SAME mapping per 16x8 k-half.
    int g  = lane >> 2;
    int tc = (lane & 3) * 2;
    float dv0 = dinv_s[r0 + g];
    float dv1 = dinv_s[r0 + 8 + g];

    unsigned a2f[4][4];                  // [kk][a0,a1,a2,a3]
    #pragma unroll
    for (int nn = 0; nn < 8; nn++) {
        int col = nn * 8 + tc;
        float h0 = fmaxf(dv0 * c1[nn][0] + b1s[col],     0.0f);
        float h1 = fmaxf(dv0 * c1[nn][1] + b1s[col + 1], 0.0f);
        float h2 = fmaxf(dv1 * c1[nn][2] + b1s[col],     0.0f);
        float h3 = fmaxf(dv1 * c1[nn][3] + b1s[col + 1], 0.0f);
        __half2 p01 = __floats2half2_rn(h0, h1);
        __half2 p23 = __floats2half2_rn(h2, h3);
        int kk = nn >> 1, hi = nn & 1;
        a2f[kk][hi * 2]     = *reinterpret_cast<unsigned*>(&p01);
        a2f[kk][hi * 2 + 1] = *reinterpret_cast<unsigned*>(&p23);
    }

    // ---- phase 2: C2[16x32] = H1[16x64] @ W2h[64x32], 16 x mma.m16n8k16 ----
    float c2[4][4];
    #pragma unroll
    for (int nn = 0; nn < 4; nn++)
        c2[nn][0] = c2[nn][1] = c2[nn][2] = c2[nn][3] = 0.0f;

    #pragma unroll
    for (int kk = 0; kk < 4; kk++) {
        #pragma unroll
        for (int nn = 0; nn < 4; nn++) {
            unsigned b0, b1r;
            unsigned addr = smem_u32(&W2h[kk * 16 + (lane & 15)][nn * 8]);
            asm volatile("ldmatrix.sync.aligned.m8n8.x2.trans.shared.b16 {%0,%1}, [%2];"
                         : "=r"(b0), "=r"(b1r) : "r"(addr));
            asm volatile(
                "mma.sync.aligned.m16n8k16.row.col.f32.f16.f16.f32 "
                "{%0,%1,%2,%3}, {%4,%5,%6,%7}, {%8,%9}, {%0,%1,%2,%3};"
                : "+f"(c2[nn][0]), "+f"(c2[nn][1]), "+f"(c2[nn][2]), "+f"(c2[nn][3])
                : "r"(a2f[kk][0]), "r"(a2f[kk][1]), "r"(a2f[kk][2]), "r"(a2f[kk][3]),
                  "r"(b0), "r"(b1r));
        }
    }

    // ---- epilogue 2: g2 = c2 * dinv -> fp16 store (g2h and s2h) ------------
    int node0 = blockbase + r0 + g;
    int node1 = node0 + 8;
    #pragma unroll
    for (int nn = 0; nn < 4; nn++) {
        int col = nn * 8 + tc;
        __half2 v0 = __floats2half2_rn(c2[nn][0] * dv0, c2[nn][1] * dv0);
        __half2 v1 = __floats2half2_rn(c2[nn][2] * dv1, c2[nn][3] * dv1);
        if (node0 < n) {
            *reinterpret_cast<__half2*>(&d_g2h[(node0 << 5) + col]) = v0;
            *reinterpret_cast<__half2*>(&d_s2h[(node0 << 5) + col]) = v0;
        }
        if (node1 < n) {
            *reinterpret_cast<__half2*>(&d_g2h[(node1 << 5) + col]) = v1;
            *reinterpret_cast<__half2*>(&d_s2h[(node1 << 5) + col]) = v1;
        }
    }
}

// ---- layer-2 scatter: s2h[dst] += g2h[src], 4 red.v4.f16x2 / edge ----------

__global__ void k_scatter32h(const int* __restrict__ src,
                             const int* __restrict__ dst, int E) {
    long long idx = (long long)blockIdx.x * blockDim.x + threadIdx.x;
    int e = (int)(idx >> 2);
    int c = (int)(idx & 3);
    if (e >= E) return;
    int u = src[e], v = dst[e];
    uint4 val = reinterpret_cast<const uint4*>(d_g2h)[(long long)u * 4 + c];
    red_add_v4h2(&reinterpret_cast<uint4*>(d_s2h)[(long long)v * 4 + c], val);
}

// ---- final: relu + classifier + log_softmax + cnt reset (thread/node) ------

__global__ void k_final(const float* __restrict__ b2,
                        const float* __restrict__ Wc,
                        const float* __restrict__ bc,
                        float* __restrict__ out, int n) {
    int node = blockIdx.x * blockDim.x + threadIdx.x;
    if (node >= n) return;

    float dv = d_dinv[node];
    const uint4* s4 = reinterpret_cast<const uint4*>(d_s2h) + (long long)node * 4;
    float l0 = bc[0], l1 = bc[1];

    #pragma unroll
    for (int j = 0; j < 4; j++) {
        uint4 q = s4[j];
        unsigned w[4] = {q.x, q.y, q.z, q.w};
        #pragma unroll
        for (int t = 0; t < 4; t++) {
            float2 v = __half22float2(*reinterpret_cast<const __half2*>(&w[t]));
            int k = j * 8 + t * 2;
            float h0 = fmaxf(dv * v.x + b2[k],     0.0f);
            float h1 = fmaxf(dv * v.y + b2[k + 1], 0.0f);
            l0 += h0 * Wc[k * 2]     + h1 * Wc[k * 2 + 2];
            l1 += h0 * Wc[k * 2 + 1] + h1 * Wc[k * 2 + 3];
        }
    }

    float m   = fmaxf(l0, l1);
    float lse = m + logf(expf(l0 - m) + expf(l1 - m));
    out[(long long)node * 2]     = l0 - lse;
    out[(long long)node * 2 + 1] = l1 - lse;
    d_cnt[node] = 0;   // reset histogram for next replay (deterministic)
}

// ---- launch ----------------------------------------------------------------

extern "C" void kernel_launch(void* const* d_in, const int* in_sizes, int n_in,
                              void* d_out, int out_size) {
    const float* x  = (const float*)d_in[0];
    const int*   ei = (const int*)  d_in[1];
    const float* W1 = (const float*)d_in[2];
    const float* b1 = (const float*)d_in[3];
    const float* W2 = (const float*)d_in[4];
    const float* b2 = (const float*)d_in[5];
    const float* Wc = (const float*)d_in[6];
    const float* bc = (const float*)d_in[7];
    float* out = (float*)d_out;

    int n = in_sizes[0] / 7;     // 100000
    int E = in_sizes[1] / 2;     // 1600000
    const int* src = ei;
    const int* dst = ei + E;

    const int T = 256;

    bool vec_ok = (E % 4 == 0) && ((((unsigned long long)dst) & 15ull) == 0);
    if (vec_ok) {
        int E4 = E / 4;
        k_count_v4<<<(E4 + T - 1) / T, T>>>((const int4*)dst, E4);
    } else {
        k_count_sc<<<(E + T - 1) / T, T>>>(dst, E);
    }

    k_prep<<<(n + T - 1) / T, T>>>(x, n);

    k_scatter16h<<<(E + T - 1) / T, T>>>(src, dst, E);

    k_transform<<<(n + 127) / 128, T>>>(W1, b1, W2, n);

    long long w2 = (long long)E * 4;
    k_scatter32h<<<(unsigned)((w2 + T - 1) / T), T>>>(src, dst, E);

    k_final<<<(n + T - 1) / T, T>>>(b2, Wc, bc, out, n);
}